// round 13
// baseline (speedup 1.0000x reference)
#include <cuda_runtime.h>
#include <cuda_bf16.h>

// TopKPool, 2 kernels with PDL:
//   K1: FINE-GRAINED streaming scorer — 2048 independent blocks x 32 K-rows
//       (multi-wave, straggler-averaging), writes packed u64 score keys directly
//       to g_keys (no smem tournament, no syncthreads, no fences), zeros attn.
//   K2: 512 blocks (4 per batch row), PDL. Each block merges the row's 512 keys
//       (16/lane, L2-hot) and gathers its 48-float4-column slice of the pooled mean.
// Output layout: [pooled (B*D) | attn_weights (B*K)], fp32.

#define NEG_INF  (-1e30f)

constexpr int Bv = 128;
constexpr int Kv = 512;
constexpr int Dv = 768;
constexpr int D4 = Dv / 4;            // 192 float4 per row
constexpr int MAX_TOPK = 64;

constexpr int SEGS  = 16;             // K1 segments per batch row
constexpr int SROWS = Kv / SEGS;      // 32 K-rows per K1 block
constexpr int T1    = 256;            // 8 warps
constexpr int QS    = 4;              // column quarters per row (K2)
constexpr int CQ    = D4 / QS;        // 48 float4 columns per K2 block
constexpr int T2    = 128;            // 4 warps

// packed score keys: key = (orderable(score) << 32) | ~idx   (max-key = best)
__device__ unsigned long long g_keys[Bv * Kv];   // 512 KB, L2-resident

__device__ __forceinline__ int clamp_ksel(int k) {
    if (k < 1) k = 1;
    if (k > MAX_TOPK) k = MAX_TOPK;
    return k;
}

__device__ __forceinline__ unsigned long long pack_key(float v, int idx) {
    unsigned u = __float_as_uint(v);
    u = (u & 0x80000000u) ? ~u : (u | 0x80000000u);   // order-preserving map
    return ((unsigned long long)u << 32) | (unsigned)(~idx);   // tie -> lower idx
}

// ---------------- K1: fine-grained streaming scorer ----------------
__global__ __launch_bounds__(T1)
void score_kernel(const float* __restrict__ emb,
                  const int*   __restrict__ mask,
                  const float* __restrict__ w,
                  const float* __restrict__ bias,
                  float*       __restrict__ out)
{
#if __CUDA_ARCH__ >= 900
    cudaTriggerProgrammaticLaunchCompletion();    // let K2 launch in our last wave
#endif
    const int tid  = threadIdx.x;
    const int lane = tid & 31;
    const int wid  = tid >> 5;

    const int b   = blockIdx.x >> 4;              // batch row
    const int k0  = (blockIdx.x & 15) * SROWS;    // segment base

    const float4* wg = (const float4*)w;
    const float4 w0 = __ldg(&wg[  0 + lane]);
    const float4 w1 = __ldg(&wg[ 32 + lane]);
    const float4 w2 = __ldg(&wg[ 64 + lane]);
    const float4 w3 = __ldg(&wg[ 96 + lane]);
    const float4 w4 = __ldg(&wg[128 + lane]);
    const float4 w5 = __ldg(&wg[160 + lane]);

    const float  bval = __ldg(&bias[0]);
    const float* eb   = emb + (size_t)b * Kv * Dv;

    // zero this block's 32-entry chunk of the attn row (d_out is poisoned)
    float* out_attn = out + (size_t)Bv * Dv;
    if (tid < SROWS)
        out_attn[(size_t)b * Kv + k0 + tid] = 0.f;

    // 8 warps x 2 iterations x 2 rows = 32 rows; no barriers, no epilogue
    #pragma unroll 1
    for (int kk = wid; kk < SROWS / 2; kk += 8) {
        const int ka = k0 + kk;
        const int kb = k0 + kk + SROWS / 2;
        const float4* ra = (const float4*)(eb + (size_t)ka * Dv);
        const float4* rb = (const float4*)(eb + (size_t)kb * Dv);

        float4 a0 = __ldcs(&ra[  0 + lane]);
        float4 a1 = __ldcs(&ra[ 32 + lane]);
        float4 a2 = __ldcs(&ra[ 64 + lane]);
        float4 a3 = __ldcs(&ra[ 96 + lane]);
        float4 a4 = __ldcs(&ra[128 + lane]);
        float4 a5 = __ldcs(&ra[160 + lane]);
        float4 b0 = __ldcs(&rb[  0 + lane]);
        float4 b1 = __ldcs(&rb[ 32 + lane]);
        float4 b2 = __ldcs(&rb[ 64 + lane]);
        float4 b3 = __ldcs(&rb[ 96 + lane]);
        float4 b4 = __ldcs(&rb[128 + lane]);
        float4 b5 = __ldcs(&rb[160 + lane]);

        float acc_a = a0.x*w0.x + a0.y*w0.y + a0.z*w0.z + a0.w*w0.w
                    + a1.x*w1.x + a1.y*w1.y + a1.z*w1.z + a1.w*w1.w
                    + a2.x*w2.x + a2.y*w2.y + a2.z*w2.z + a2.w*w2.w
                    + a3.x*w3.x + a3.y*w3.y + a3.z*w3.z + a3.w*w3.w
                    + a4.x*w4.x + a4.y*w4.y + a4.z*w4.z + a4.w*w4.w
                    + a5.x*w5.x + a5.y*w5.y + a5.z*w5.z + a5.w*w5.w;
        float acc_b = b0.x*w0.x + b0.y*w0.y + b0.z*w0.z + b0.w*w0.w
                    + b1.x*w1.x + b1.y*w1.y + b1.z*w1.z + b1.w*w1.w
                    + b2.x*w2.x + b2.y*w2.y + b2.z*w2.z + b2.w*w2.w
                    + b3.x*w3.x + b3.y*w3.y + b3.z*w3.z + b3.w*w3.w
                    + b4.x*w4.x + b4.y*w4.y + b4.z*w4.z + b4.w*w4.w
                    + b5.x*w5.x + b5.y*w5.y + b5.z*w5.z + b5.w*w5.w;

        #pragma unroll
        for (int off = 16; off; off >>= 1) {
            acc_a += __shfl_xor_sync(0xFFFFFFFFu, acc_a, off);
            acc_b += __shfl_xor_sync(0xFFFFFFFFu, acc_b, off);
        }
        if (lane == 0) {
            float sa = acc_a + bval;
            float sb = acc_b + bval;
            if (__ldg(&mask[(size_t)b * Kv + ka]) == 0) sa = NEG_INF;
            if (__ldg(&mask[(size_t)b * Kv + kb]) == 0) sb = NEG_INF;
            g_keys[(size_t)b * Kv + ka] = pack_key(sa, ka);
            g_keys[(size_t)b * Kv + kb] = pack_key(sb, kb);
        }
    }
}

// ---------------- K2: 4 blocks per row, full-key merge + sliced gather ----------------
__global__ __launch_bounds__(T2)
void finish_kernel(const float* __restrict__ emb,
                   const int*   __restrict__ topk,
                   float*       __restrict__ out)
{
    __shared__ int s_gk[MAX_TOPK];

    const int b    = blockIdx.x >> 2;            // batch row
    const int q    = blockIdx.x & 3;             // column quarter
    const int tid  = threadIdx.x;
    const int lane = tid & 31;
    const int wid  = tid >> 5;

    // ---- preamble (independent of K1; overlaps K1's last wave under PDL) ----
    const int ksel = clamp_ksel(__ldg(&topk[0]));
    const float inv = 1.f / (float)ksel;

    float* out_pool = out;                       // (B, D)
    float* out_attn = out + (size_t)Bv * Dv;     // (B, K)
    const float4* ebv = (const float4*)(emb + (size_t)b * Kv * Dv);
    const unsigned long long* kb = g_keys + (size_t)b * Kv;

#if __CUDA_ARCH__ >= 900
    cudaGridDependencySynchronize();             // wait for K1 (memory visible)
#endif

    // ---- merge: warp 0, 16 keys/lane over all 512 (L2-hot, coalesced) ----
    if (wid == 0) {
        unsigned long long key[16];
        #pragma unroll
        for (int j = 0; j < 16; j++)
            key[j] = __ldcg(&kb[lane + 32 * j]);

        for (int m = 0; m < ksel; m++) {
            unsigned long long best = key[0];
            #pragma unroll
            for (int j = 1; j < 16; j++) if (key[j] > best) best = key[j];
            #pragma unroll
            for (int off = 16; off; off >>= 1) {
                unsigned long long o = __shfl_xor_sync(0xFFFFFFFFu, best, off);
                if (o > best) best = o;
            }
            #pragma unroll
            for (int j = 0; j < 16; j++) if (key[j] == best) key[j] = 0ull;
            if (lane == 0) s_gk[m] = (int)(~(unsigned)(best & 0xFFFFFFFFull));
        }
    }
    __syncthreads();

    // indicators: only quarter 0 writes (row zeroed by K1)
    if (q == 0 && tid < ksel)
        out_attn[(size_t)b * Kv + s_gk[tid]] = inv;

    // sliced gather: this block owns float4 columns [q*CQ, (q+1)*CQ)
    if (tid < CQ) {
        const int col = q * CQ + tid;
        float4 sum = make_float4(0.f, 0.f, 0.f, 0.f);
        if (ksel == 8) {
            int ix[8];
            #pragma unroll
            for (int m = 0; m < 8; m++) ix[m] = s_gk[m];
            #pragma unroll
            for (int m = 0; m < 8; m++) {
                float4 e = __ldg(&ebv[(size_t)ix[m] * D4 + col]);
                sum.x += e.x; sum.y += e.y; sum.z += e.z; sum.w += e.w;
            }
        } else {
            #pragma unroll 4
            for (int m = 0; m < ksel; m++) {
                float4 e = __ldg(&ebv[(size_t)s_gk[m] * D4 + col]);
                sum.x += e.x; sum.y += e.y; sum.z += e.z; sum.w += e.w;
            }
        }
        float4 r = make_float4(sum.x * inv, sum.y * inv, sum.z * inv, sum.w * inv);
        ((float4*)(out_pool + (size_t)b * Dv))[col] = r;
    }
}

extern "C" void kernel_launch(void* const* d_in, const int* in_sizes, int n_in,
                              void* d_out, int out_size)
{
    const float* emb  = (const float*)d_in[0];
    const int*   mask = (const int*)  d_in[1];
    const float* w    = (const float*)d_in[2];
    const float* bias = (const float*)d_in[3];
    const int*   topk = (const int*)  d_in[4];
    float*       out  = (float*)d_out;
    (void)in_sizes; (void)n_in; (void)out_size;

    score_kernel<<<Bv * SEGS, T1>>>(emb, mask, w, bias, out);

    // K2 with programmatic dependent launch: overlaps launch+preamble with K1 tail
    cudaLaunchConfig_t cfg = {};
    cfg.gridDim  = dim3(Bv * QS, 1, 1);
    cfg.blockDim = dim3(T2, 1, 1);
    cfg.dynamicSmemBytes = 0;
    cfg.stream = 0;
    cudaLaunchAttribute attrs[1];
    attrs[0].id = cudaLaunchAttributeProgrammaticStreamSerialization;
    attrs[0].val.programmaticStreamSerializationAllowed = 1;
    cfg.attrs = attrs;
    cfg.numAttrs = 1;
    cudaError_t err = cudaLaunchKernelEx(&cfg, finish_kernel, emb, topk, out);
    if (err != cudaSuccess) {
        finish_kernel<<<Bv * QS, T2>>>(emb, topk, out);
    }
}

// round 14
// speedup vs baseline: 1.0872x; 1.0872x over previous
#include <cuda_runtime.h>
#include <cuda_bf16.h>

// TopKPool, 2 kernels with PDL (R11 structure, K2 merge -> warp bitonic sort):
//   K1: masked linear scores (201 MB stream @ ~6.1 TB/s, chip DRAM-bound),
//       per-segment top-ksel candidates as packed u64 keys, attn zeroing.
//   K2: 512 blocks (4 per batch row). Bitonic-sorts the row's 32 candidate keys
//       in ONE warp pass (~300 cyc vs ~2000 for 8 knockout rounds — the tail runs
//       at DVFS-depressed clocks, so cycles on the critical path are 2.5-3x dearer),
//       then gathers its 48-float4-column slice of the pooled mean.
// Output layout: [pooled (B*D) | attn_weights (B*K)], fp32.

#define NEG_INF  (-1e30f)

constexpr int Bv = 128;
constexpr int Kv = 512;
constexpr int Dv = 768;
constexpr int D4 = Dv / 4;            // 192 float4 per row
constexpr int MAX_TOPK = 64;

constexpr int SPLIT = 4;              // K-segments per batch row (K1)
constexpr int KSEG  = Kv / SPLIT;     // 128 rows per K1 block
constexpr int T1    = 256;            // 8 warps
constexpr int QS    = 4;              // column quarters per row (K2)
constexpr int CQ    = D4 / QS;        // 48 float4 columns per K2 block
constexpr int T2    = 128;            // 4 warps

// packed candidates: key = (orderable(score) << 32) | ~idx   (max-key = best)
__device__ unsigned long long g_cand[Bv * SPLIT * MAX_TOPK];

__device__ __forceinline__ int clamp_ksel(int k) {
    if (k < 1) k = 1;
    if (k > MAX_TOPK) k = MAX_TOPK;
    return k;
}

__device__ __forceinline__ unsigned long long pack_key(float v, int idx) {
    unsigned u = __float_as_uint(v);
    u = (u & 0x80000000u) ? ~u : (u | 0x80000000u);   // order-preserving map
    return ((unsigned long long)u << 32) | (unsigned)(~idx);   // tie -> lower idx
}

// ---------------- K1: scoring + per-segment top-k (R11, proven) ----------------
__global__ __launch_bounds__(T1)
void score_kernel(const float* __restrict__ emb,
                  const int*   __restrict__ mask,
                  const float* __restrict__ w,
                  const float* __restrict__ bias,
                  const int*   __restrict__ topk,
                  float*       __restrict__ out)
{
#if __CUDA_ARCH__ >= 900
    cudaTriggerProgrammaticLaunchCompletion();    // let K2 launch early
#endif
    __shared__ float s_sc[KSEG];

    const int tid  = threadIdx.x;
    const int lane = tid & 31;
    const int wid  = tid >> 5;

    const int b   = blockIdx.x >> 2;
    const int seg = blockIdx.x & 3;
    const int k0  = seg * KSEG;

    const float4* wg = (const float4*)w;
    const float4 w0 = __ldg(&wg[  0 + lane]);
    const float4 w1 = __ldg(&wg[ 32 + lane]);
    const float4 w2 = __ldg(&wg[ 64 + lane]);
    const float4 w3 = __ldg(&wg[ 96 + lane]);
    const float4 w4 = __ldg(&wg[128 + lane]);
    const float4 w5 = __ldg(&wg[160 + lane]);

    const float  bval = __ldg(&bias[0]);
    const float* eb   = emb + (size_t)b * Kv * Dv;

    float* out_attn = out + (size_t)Bv * Dv;

    for (int kk = wid; kk < KSEG / 2; kk += 8) {
        const int ka = kk;
        const int kb = kk + KSEG / 2;
        const float4* ra = (const float4*)(eb + (size_t)(k0 + ka) * Dv);
        const float4* rb = (const float4*)(eb + (size_t)(k0 + kb) * Dv);

        float4 a0 = __ldcs(&ra[  0 + lane]);
        float4 a1 = __ldcs(&ra[ 32 + lane]);
        float4 a2 = __ldcs(&ra[ 64 + lane]);
        float4 a3 = __ldcs(&ra[ 96 + lane]);
        float4 a4 = __ldcs(&ra[128 + lane]);
        float4 a5 = __ldcs(&ra[160 + lane]);
        float4 b0 = __ldcs(&rb[  0 + lane]);
        float4 b1 = __ldcs(&rb[ 32 + lane]);
        float4 b2 = __ldcs(&rb[ 64 + lane]);
        float4 b3 = __ldcs(&rb[ 96 + lane]);
        float4 b4 = __ldcs(&rb[128 + lane]);
        float4 b5 = __ldcs(&rb[160 + lane]);

        float acc_a = a0.x*w0.x + a0.y*w0.y + a0.z*w0.z + a0.w*w0.w
                    + a1.x*w1.x + a1.y*w1.y + a1.z*w1.z + a1.w*w1.w
                    + a2.x*w2.x + a2.y*w2.y + a2.z*w2.z + a2.w*w2.w
                    + a3.x*w3.x + a3.y*w3.y + a3.z*w3.z + a3.w*w3.w
                    + a4.x*w4.x + a4.y*w4.y + a4.z*w4.z + a4.w*w4.w
                    + a5.x*w5.x + a5.y*w5.y + a5.z*w5.z + a5.w*w5.w;
        float acc_b = b0.x*w0.x + b0.y*w0.y + b0.z*w0.z + b0.w*w0.w
                    + b1.x*w1.x + b1.y*w1.y + b1.z*w1.z + b1.w*w1.w
                    + b2.x*w2.x + b2.y*w2.y + b2.z*w2.z + b2.w*w2.w
                    + b3.x*w3.x + b3.y*w3.y + b3.z*w3.z + b3.w*w3.w
                    + b4.x*w4.x + b4.y*w4.y + b4.z*w4.z + b4.w*w4.w
                    + b5.x*w5.x + b5.y*w5.y + b5.z*w5.z + b5.w*w5.w;

        #pragma unroll
        for (int off = 16; off; off >>= 1) {
            acc_a += __shfl_xor_sync(0xFFFFFFFFu, acc_a, off);
            acc_b += __shfl_xor_sync(0xFFFFFFFFu, acc_b, off);
        }
        if (lane == 0) {
            float sa = acc_a + bval;
            float sb = acc_b + bval;
            if (__ldg(&mask[(size_t)b * Kv + k0 + ka]) == 0) sa = NEG_INF;
            if (__ldg(&mask[(size_t)b * Kv + k0 + kb]) == 0) sb = NEG_INF;
            s_sc[ka] = sa;
            s_sc[kb] = sb;
        }
    }

    // zero this block's chunk of the attn row (d_out is poisoned)
    for (int i = tid; i < KSEG; i += T1)
        out_attn[(size_t)b * Kv + k0 + i] = 0.f;

    __syncthreads();

    // per-segment top-ksel: tournament on packed u64 keys (warp 0)
    if (wid == 0) {
        int ksel = clamp_ksel(__ldg(&topk[0]));

        unsigned long long key[4];
        #pragma unroll
        for (int j = 0; j < 4; j++)
            key[j] = pack_key(s_sc[lane + 32 * j], k0 + lane + 32 * j);

        unsigned long long* cd = g_cand + (size_t)(b * SPLIT + seg) * MAX_TOPK;

        for (int m = 0; m < ksel; m++) {
            unsigned long long best = key[0];
            #pragma unroll
            for (int j = 1; j < 4; j++) if (key[j] > best) best = key[j];
            #pragma unroll
            for (int off = 16; off; off >>= 1) {
                unsigned long long o = __shfl_xor_sync(0xFFFFFFFFu, best, off);
                if (o > best) best = o;
            }
            #pragma unroll
            for (int j = 0; j < 4; j++) if (key[j] == best) key[j] = 0ull;
            if (lane == 0) cd[m] = best;
        }
    }
}

// ---------------- K2: 4 blocks per row, bitonic merge + sliced gather ----------------
__global__ __launch_bounds__(T2)
void finish_kernel(const float* __restrict__ emb,
                   const int*   __restrict__ topk,
                   float*       __restrict__ out)
{
    __shared__ int s_gk[MAX_TOPK];

    const int b    = blockIdx.x >> 2;            // batch row
    const int q    = blockIdx.x & 3;             // column quarter
    const int tid  = threadIdx.x;
    const int lane = tid & 31;
    const int wid  = tid >> 5;

    // ---- preamble (independent of K1; runs during K1's tail under PDL) ----
    const int ksel = clamp_ksel(__ldg(&topk[0]));
    const int C    = SPLIT * ksel;
    const float inv = 1.f / (float)ksel;

    float* out_pool = out;                       // (B, D)
    float* out_attn = out + (size_t)Bv * Dv;     // (B, K)
    const float4* ebv = (const float4*)(emb + (size_t)b * Kv * Dv);
    const unsigned long long* cd = g_cand + (size_t)b * SPLIT * MAX_TOPK;

#if __CUDA_ARCH__ >= 900
    cudaGridDependencySynchronize();             // wait for K1 (memory visible)
#endif

    if (wid == 0) {
        if (C <= 32) {
            // ---- bitonic sort (descending), 15 stages, lane m = m-th largest ----
            unsigned long long key = 0ull;       // pad keys sink to the end
            if (lane < C) {
                int sg = lane / ksel, m = lane - sg * ksel;
                key = __ldcg(&cd[(size_t)sg * MAX_TOPK + m]);
            }
            #pragma unroll
            for (int k = 2; k <= 32; k <<= 1) {
                #pragma unroll
                for (int j = k >> 1; j > 0; j >>= 1) {
                    unsigned long long o = __shfl_xor_sync(0xFFFFFFFFu, key, j);
                    bool up      = ((lane & k) == 0);     // descending block
                    bool takeMax = up ? ((lane & j) == 0) : ((lane & j) != 0);
                    key = takeMax ? (key > o ? key : o) : (key < o ? key : o);
                }
            }
            if (lane < ksel)
                s_gk[lane] = (int)(~(unsigned)(key & 0xFFFFFFFFull));
        } else {
            // fallback (ksel > 8): knockout rounds over up to 256 candidates
            unsigned long long key[8];
            #pragma unroll
            for (int j = 0; j < 8; j++) {
                int n = lane + 32 * j;
                if (n < C) {
                    int sg = n / ksel, m = n - sg * ksel;
                    key[j] = __ldcg(&cd[(size_t)sg * MAX_TOPK + m]);
                } else key[j] = 0ull;
            }
            for (int m = 0; m < ksel; m++) {
                unsigned long long best = key[0];
                #pragma unroll
                for (int j = 1; j < 8; j++) if (key[j] > best) best = key[j];
                #pragma unroll
                for (int off = 16; off; off >>= 1) {
                    unsigned long long o = __shfl_xor_sync(0xFFFFFFFFu, best, off);
                    if (o > best) best = o;
                }
                #pragma unroll
                for (int j = 0; j < 8; j++) if (key[j] == best) key[j] = 0ull;
                if (lane == 0) s_gk[m] = (int)(~(unsigned)(best & 0xFFFFFFFFull));
            }
        }
    }
    __syncthreads();

    // indicators: only quarter 0 writes (row zeroed by K1)
    if (q == 0 && tid < ksel)
        out_attn[(size_t)b * Kv + s_gk[tid]] = inv;

    // sliced gather: this block owns float4 columns [q*CQ, (q+1)*CQ)
    if (tid < CQ) {
        const int col = q * CQ + tid;
        float4 sum = make_float4(0.f, 0.f, 0.f, 0.f);
        if (ksel == 8) {
            int ix[8];
            #pragma unroll
            for (int m = 0; m < 8; m++) ix[m] = s_gk[m];
            #pragma unroll
            for (int m = 0; m < 8; m++) {
                float4 e = __ldg(&ebv[(size_t)ix[m] * D4 + col]);
                sum.x += e.x; sum.y += e.y; sum.z += e.z; sum.w += e.w;
            }
        } else {
            #pragma unroll 4
            for (int m = 0; m < ksel; m++) {
                float4 e = __ldg(&ebv[(size_t)s_gk[m] * D4 + col]);
                sum.x += e.x; sum.y += e.y; sum.z += e.z; sum.w += e.w;
            }
        }
        float4 r = make_float4(sum.x * inv, sum.y * inv, sum.z * inv, sum.w * inv);
        ((float4*)(out_pool + (size_t)b * Dv))[col] = r;
    }
}

extern "C" void kernel_launch(void* const* d_in, const int* in_sizes, int n_in,
                              void* d_out, int out_size)
{
    const float* emb  = (const float*)d_in[0];
    const int*   mask = (const int*)  d_in[1];
    const float* w    = (const float*)d_in[2];
    const float* bias = (const float*)d_in[3];
    const int*   topk = (const int*)  d_in[4];
    float*       out  = (float*)d_out;
    (void)in_sizes; (void)n_in; (void)out_size;

    score_kernel<<<Bv * SPLIT, T1>>>(emb, mask, w, bias, topk, out);

    // K2 with programmatic dependent launch: overlaps launch+preamble with K1 tail
    cudaLaunchConfig_t cfg = {};
    cfg.gridDim  = dim3(Bv * QS, 1, 1);
    cfg.blockDim = dim3(T2, 1, 1);
    cfg.dynamicSmemBytes = 0;
    cfg.stream = 0;
    cudaLaunchAttribute attrs[1];
    attrs[0].id = cudaLaunchAttributeProgrammaticStreamSerialization;
    attrs[0].val.programmaticStreamSerializationAllowed = 1;
    cfg.attrs = attrs;
    cfg.numAttrs = 1;
    cudaError_t err = cudaLaunchKernelEx(&cfg, finish_kernel, emb, topk, out);
    if (err != cudaSuccess) {
        finish_kernel<<<Bv * QS, T2>>>(emb, topk, out);
    }
}

// round 15
// speedup vs baseline: 1.1022x; 1.0138x over previous
#include <cuda_runtime.h>
#include <cuda_bf16.h>

// TopKPool, 2 kernels with PDL (R11 structure + gather-latency cuts):
//   K1: masked linear scores (201 MB stream, DRAM-bound ~6.1 TB/s). Default cache
//       policy (no __ldcs) so the tail's candidate rows stay L2-resident.
//       Per-segment top-ksel candidates packed contiguously (row = 4*ksel keys).
//   K2: 512 blocks (4/row). Bitonic-sorts the row's 32 candidate keys in one warp
//       pass, then gathers its 48-float4-column slice — now mostly L2 hits.
// Output layout: [pooled (B*D) | attn_weights (B*K)], fp32.

#define NEG_INF  (-1e30f)

constexpr int Bv = 128;
constexpr int Kv = 512;
constexpr int Dv = 768;
constexpr int D4 = Dv / 4;            // 192 float4 per row
constexpr int MAX_TOPK = 64;

constexpr int SPLIT = 4;              // K-segments per batch row (K1)
constexpr int KSEG  = Kv / SPLIT;     // 128 rows per K1 block
constexpr int T1    = 256;            // 8 warps
constexpr int QS    = 4;              // column quarters per row (K2)
constexpr int CQ    = D4 / QS;        // 48 float4 columns per K2 block
constexpr int T2    = 128;            // 4 warps

// packed candidates, contiguous: g_cand[(b*SPLIT+seg)*ksel + m]
// key = (orderable(score) << 32) | ~idx   (max-key = best, ties -> lower idx)
__device__ unsigned long long g_cand[Bv * SPLIT * MAX_TOPK];

__device__ __forceinline__ int clamp_ksel(int k) {
    if (k < 1) k = 1;
    if (k > MAX_TOPK) k = MAX_TOPK;
    return k;
}

__device__ __forceinline__ unsigned long long pack_key(float v, int idx) {
    unsigned u = __float_as_uint(v);
    u = (u & 0x80000000u) ? ~u : (u | 0x80000000u);   // order-preserving map
    return ((unsigned long long)u << 32) | (unsigned)(~idx);
}

// ---------------- K1: scoring + per-segment top-k ----------------
__global__ __launch_bounds__(T1)
void score_kernel(const float* __restrict__ emb,
                  const int*   __restrict__ mask,
                  const float* __restrict__ w,
                  const float* __restrict__ bias,
                  const int*   __restrict__ topk,
                  float*       __restrict__ out)
{
#if __CUDA_ARCH__ >= 900
    cudaTriggerProgrammaticLaunchCompletion();    // let K2 launch early
#endif
    __shared__ float s_sc[KSEG];

    const int tid  = threadIdx.x;
    const int lane = tid & 31;
    const int wid  = tid >> 5;

    const int b   = blockIdx.x >> 2;
    const int seg = blockIdx.x & 3;
    const int k0  = seg * KSEG;

    const float4* wg = (const float4*)w;
    const float4 w0 = __ldg(&wg[  0 + lane]);
    const float4 w1 = __ldg(&wg[ 32 + lane]);
    const float4 w2 = __ldg(&wg[ 64 + lane]);
    const float4 w3 = __ldg(&wg[ 96 + lane]);
    const float4 w4 = __ldg(&wg[128 + lane]);
    const float4 w5 = __ldg(&wg[160 + lane]);

    const float  bval = __ldg(&bias[0]);
    const float* eb   = emb + (size_t)b * Kv * Dv;

    float* out_attn = out + (size_t)Bv * Dv;

    for (int kk = wid; kk < KSEG / 2; kk += 8) {
        const int ka = kk;
        const int kb = kk + KSEG / 2;
        const float4* ra = (const float4*)(eb + (size_t)(k0 + ka) * Dv);
        const float4* rb = (const float4*)(eb + (size_t)(k0 + kb) * Dv);

        // default cache policy: keep streamed rows L2-resident for K2's gather
        float4 a0 = __ldg(&ra[  0 + lane]);
        float4 a1 = __ldg(&ra[ 32 + lane]);
        float4 a2 = __ldg(&ra[ 64 + lane]);
        float4 a3 = __ldg(&ra[ 96 + lane]);
        float4 a4 = __ldg(&ra[128 + lane]);
        float4 a5 = __ldg(&ra[160 + lane]);
        float4 b0 = __ldg(&rb[  0 + lane]);
        float4 b1 = __ldg(&rb[ 32 + lane]);
        float4 b2 = __ldg(&rb[ 64 + lane]);
        float4 b3 = __ldg(&rb[ 96 + lane]);
        float4 b4 = __ldg(&rb[128 + lane]);
        float4 b5 = __ldg(&rb[160 + lane]);

        float acc_a = a0.x*w0.x + a0.y*w0.y + a0.z*w0.z + a0.w*w0.w
                    + a1.x*w1.x + a1.y*w1.y + a1.z*w1.z + a1.w*w1.w
                    + a2.x*w2.x + a2.y*w2.y + a2.z*w2.z + a2.w*w2.w
                    + a3.x*w3.x + a3.y*w3.y + a3.z*w3.z + a3.w*w3.w
                    + a4.x*w4.x + a4.y*w4.y + a4.z*w4.z + a4.w*w4.w
                    + a5.x*w5.x + a5.y*w5.y + a5.z*w5.z + a5.w*w5.w;
        float acc_b = b0.x*w0.x + b0.y*w0.y + b0.z*w0.z + b0.w*w0.w
                    + b1.x*w1.x + b1.y*w1.y + b1.z*w1.z + b1.w*w1.w
                    + b2.x*w2.x + b2.y*w2.y + b2.z*w2.z + b2.w*w2.w
                    + b3.x*w3.x + b3.y*w3.y + b3.z*w3.z + b3.w*w3.w
                    + b4.x*w4.x + b4.y*w4.y + b4.z*w4.z + b4.w*w4.w
                    + b5.x*w5.x + b5.y*w5.y + b5.z*w5.z + b5.w*w5.w;

        #pragma unroll
        for (int off = 16; off; off >>= 1) {
            acc_a += __shfl_xor_sync(0xFFFFFFFFu, acc_a, off);
            acc_b += __shfl_xor_sync(0xFFFFFFFFu, acc_b, off);
        }
        if (lane == 0) {
            float sa = acc_a + bval;
            float sb = acc_b + bval;
            if (__ldg(&mask[(size_t)b * Kv + k0 + ka]) == 0) sa = NEG_INF;
            if (__ldg(&mask[(size_t)b * Kv + k0 + kb]) == 0) sb = NEG_INF;
            s_sc[ka] = sa;
            s_sc[kb] = sb;
        }
    }

    // zero this block's chunk of the attn row (d_out is poisoned)
    for (int i = tid; i < KSEG; i += T1)
        out_attn[(size_t)b * Kv + k0 + i] = 0.f;

    __syncthreads();

    // per-segment top-ksel: knockout tournament, contiguous compact output
    if (wid == 0) {
        int ksel = clamp_ksel(__ldg(&topk[0]));

        unsigned long long key[4];
        #pragma unroll
        for (int j = 0; j < 4; j++)
            key[j] = pack_key(s_sc[lane + 32 * j], k0 + lane + 32 * j);

        unsigned long long* cd = g_cand + (size_t)(b * SPLIT + seg) * ksel;

        for (int m = 0; m < ksel; m++) {
            unsigned long long best = key[0];
            #pragma unroll
            for (int j = 1; j < 4; j++) if (key[j] > best) best = key[j];
            #pragma unroll
            for (int off = 16; off; off >>= 1) {
                unsigned long long o = __shfl_xor_sync(0xFFFFFFFFu, best, off);
                if (o > best) best = o;
            }
            #pragma unroll
            for (int j = 0; j < 4; j++) if (key[j] == best) key[j] = 0ull;
            if (lane == 0) cd[m] = best;
        }
    }
}

// ---------------- K2: 4 blocks per row, bitonic merge + sliced gather ----------------
__global__ __launch_bounds__(T2)
void finish_kernel(const float* __restrict__ emb,
                   const int*   __restrict__ topk,
                   float*       __restrict__ out)
{
    __shared__ int s_gk[MAX_TOPK];

    const int b    = blockIdx.x >> 2;            // batch row
    const int q    = blockIdx.x & 3;             // column quarter
    const int tid  = threadIdx.x;
    const int lane = tid & 31;
    const int wid  = tid >> 5;

    // ---- preamble (independent of K1; runs during K1's tail under PDL) ----
    const int ksel = clamp_ksel(__ldg(&topk[0]));
    const int C    = SPLIT * ksel;
    const float inv = 1.f / (float)ksel;

    float* out_pool = out;                       // (B, D)
    float* out_attn = out + (size_t)Bv * Dv;     // (B, K)
    const float4* ebv = (const float4*)(emb + (size_t)b * Kv * Dv);
    const unsigned long long* cd = g_cand + (size_t)b * SPLIT * ksel;

#if __CUDA_ARCH__ >= 900
    cudaGridDependencySynchronize();             // wait for K1 (memory visible)
#endif

    if (wid == 0) {
        if (C <= 32) {
            // bitonic sort (descending): 2 cache lines in, lane m = m-th largest
            unsigned long long key = (lane < C) ? __ldcg(&cd[lane]) : 0ull;
            #pragma unroll
            for (int k = 2; k <= 32; k <<= 1) {
                #pragma unroll
                for (int j = k >> 1; j > 0; j >>= 1) {
                    unsigned long long o = __shfl_xor_sync(0xFFFFFFFFu, key, j);
                    bool up      = ((lane & k) == 0);
                    bool takeMax = up ? ((lane & j) == 0) : ((lane & j) != 0);
                    key = takeMax ? (key > o ? key : o) : (key < o ? key : o);
                }
            }
            if (lane < ksel)
                s_gk[lane] = (int)(~(unsigned)(key & 0xFFFFFFFFull));
        } else {
            // fallback (ksel > 8): knockout rounds over up to 256 candidates
            unsigned long long key[8];
            #pragma unroll
            for (int j = 0; j < 8; j++) {
                int n = lane + 32 * j;
                key[j] = (n < C) ? __ldcg(&cd[n]) : 0ull;
            }
            for (int m = 0; m < ksel; m++) {
                unsigned long long best = key[0];
                #pragma unroll
                for (int j = 1; j < 8; j++) if (key[j] > best) best = key[j];
                #pragma unroll
                for (int off = 16; off; off >>= 1) {
                    unsigned long long o = __shfl_xor_sync(0xFFFFFFFFu, best, off);
                    if (o > best) best = o;
                }
                #pragma unroll
                for (int j = 0; j < 8; j++) if (key[j] == best) key[j] = 0ull;
                if (lane == 0) s_gk[m] = (int)(~(unsigned)(best & 0xFFFFFFFFull));
            }
        }
    }
    __syncthreads();

    // indicators: only quarter 0 writes (row zeroed by K1)
    if (q == 0 && tid < ksel)
        out_attn[(size_t)b * Kv + s_gk[tid]] = inv;

    // sliced gather: this block owns float4 columns [q*CQ, (q+1)*CQ)
    // rows are L2-resident (K1 used default cache policy) -> ~234cy hits
    if (tid < CQ) {
        const int col = q * CQ + tid;
        float4 sum = make_float4(0.f, 0.f, 0.f, 0.f);
        if (ksel == 8) {
            int ix[8];
            #pragma unroll
            for (int m = 0; m < 8; m++) ix[m] = s_gk[m];
            #pragma unroll
            for (int m = 0; m < 8; m++) {
                float4 e = __ldg(&ebv[(size_t)ix[m] * D4 + col]);
                sum.x += e.x; sum.y += e.y; sum.z += e.z; sum.w += e.w;
            }
        } else {
            #pragma unroll 4
            for (int m = 0; m < ksel; m++) {
                float4 e = __ldg(&ebv[(size_t)s_gk[m] * D4 + col]);
                sum.x += e.x; sum.y += e.y; sum.z += e.z; sum.w += e.w;
            }
        }
        float4 r = make_float4(sum.x * inv, sum.y * inv, sum.z * inv, sum.w * inv);
        ((float4*)(out_pool + (size_t)b * Dv))[col] = r;
    }
}

extern "C" void kernel_launch(void* const* d_in, const int* in_sizes, int n_in,
                              void* d_out, int out_size)
{
    const float* emb  = (const float*)d_in[0];
    const int*   mask = (const int*)  d_in[1];
    const float* w    = (const float*)d_in[2];
    const float* bias = (const float*)d_in[3];
    const int*   topk = (const int*)  d_in[4];
    float*       out  = (float*)d_out;
    (void)in_sizes; (void)n_in; (void)out_size;

    score_kernel<<<Bv * SPLIT, T1>>>(emb, mask, w, bias, topk, out);

    // K2 with programmatic dependent launch: overlaps launch+preamble with K1 tail
    cudaLaunchConfig_t cfg = {};
    cfg.gridDim  = dim3(Bv * QS, 1, 1);
    cfg.blockDim = dim3(T2, 1, 1);
    cfg.dynamicSmemBytes = 0;
    cfg.stream = 0;
    cudaLaunchAttribute attrs[1];
    attrs[0].id = cudaLaunchAttributeProgrammaticStreamSerialization;
    attrs[0].val.programmaticStreamSerializationAllowed = 1;
    cfg.attrs = attrs;
    cfg.numAttrs = 1;
    cudaError_t err = cudaLaunchKernelEx(&cfg, finish_kernel, emb, topk, out);
    if (err != cudaSuccess) {
        finish_kernel<<<Bv * QS, T2>>>(emb, topk, out);
    }
}